// round 3
// baseline (speedup 1.0000x reference)
#include <cuda_runtime.h>
#include <stdint.h>

// Algebraic feature expansion:
//   out[:, 0:16]    = x
//   out[:, 16:136]  = pair products  x[a]*x[b]   (lex order)
//   out[:, 136:696] = triple products x[a]*x[b]*x[c] (lex order)
// B=262144 rows, 696 out cols. HBM-store-bound (~730 MB out).
//
// v3: software-pipelined tiles. Double-buffered smem row cache; next tile's
// x is prefetched into registers at the top of each iteration (LDG latency
// hidden under the 16-row compute), one __syncthreads per tile. Operand
// indices decoded once per thread; inner body per row = 12 LDS (immediate
// offsets), 8 FMUL, 1 STG.128.

#define NC    16
#define NPAIR 120
#define OUTC  696
#define Q4    174          // OUTC / 4
#define RTILE 16           // rows per tile
#define PAD   20           // floats per cached row (16 data + 1.0 dummy + pad)
#define BLK   192          // 6 warps; threads [0,174) compute, [0,64) load

__global__ __launch_bounds__(BLK) void algebraic_expand_kernel(
    const float* __restrict__ x,
    float4* __restrict__ out4,
    int nrows)
{
    __shared__ __align__(16) uint32_t stab[OUTC];
    __shared__ __align__(16) float xs[2][RTILE][PAD];

    const int t = threadIdx.x;

    // ---- Build packed index table once (a | b<<8 | c<<16; 16 = dummy -> 1.0) ----
    for (int col = t; col < OUTC; col += BLK) {
        int a, b, c;
        if (col < NC) {
            a = col; b = 16; c = 16;
        } else if (col < NC + NPAIR) {
            int p = col - NC;
            a = 0;
            for (;; a++) { int cnt = NC - 1 - a; if (p < cnt) break; p -= cnt; }
            b = a + 1 + p;
            c = 16;
        } else {
            int q = col - NC - NPAIR;
            a = 0;
            for (;; a++) {
                int m = NC - 1 - a;
                int cnt = (m * (m - 1)) >> 1;     // C(m,2)
                if (q < cnt) break;
                q -= cnt;
            }
            b = a + 1;
            for (;; b++) { int cnt = NC - 1 - b; if (q < cnt) break; q -= cnt; }
            c = b + 1 + q;
        }
        stab[col] = (uint32_t)a | ((uint32_t)b << 8) | ((uint32_t)c << 16);
    }

    // dummy operand column, never overwritten by tile loads
    if (t < RTILE) { xs[0][t][16] = 1.0f; xs[1][t][16] = 1.0f; }
    __syncthreads();

    // ---- Decode this thread's fixed chunk ONCE into register offsets ----
    const bool active = (t < Q4);
    const bool loader = (t < RTILE * NC / 4);     // 64 loader threads
    int i0=16,i1=16,i2=16,i3=16,i4=16,i5=16,i6=16,i7=16,i8=16,i9=16,ia=16,ib=16;
    if (active) {
        uint4 pk = reinterpret_cast<const uint4*>(stab)[t];
        i0 =  pk.x        & 255u;  i1 = (pk.x >>  8) & 255u;  i2 = pk.x >> 16;
        i3 =  pk.y        & 255u;  i4 = (pk.y >>  8) & 255u;  i5 = pk.y >> 16;
        i6 =  pk.z        & 255u;  i7 = (pk.z >>  8) & 255u;  i8 = pk.z >> 16;
        i9 =  pk.w        & 255u;  ia = (pk.w >>  8) & 255u;  ib = pk.w >> 16;
    }

    const int ntiles = (nrows + RTILE - 1) / RTILE;
    const int lr  = t >> 2;            // loader: row within tile
    const int lc  = (t & 3) << 2;      // loader: col within row

    // ---- Preload first tile into buffer 0 ----
    int tile = blockIdx.x;
    if (tile < ntiles && loader) {
        const int gr = tile * RTILE + lr;
        if (gr < nrows) {
            float4 v = *reinterpret_cast<const float4*>(x + (size_t)gr * NC + lc);
            *reinterpret_cast<float4*>(&xs[0][lr][lc]) = v;
        }
    }
    __syncthreads();

    int cur = 0;
    for (; tile < ntiles; tile += gridDim.x, cur ^= 1) {
        const int row0 = tile * RTILE;
        const int next = tile + gridDim.x;

        // ---- Prefetch next tile (LDG issues now, consumed after compute) ----
        float4 pre;
        const bool do_pre = loader && (next < ntiles) &&
                            (next * RTILE + lr < nrows);
        if (do_pre)
            pre = *reinterpret_cast<const float4*>(
                      x + (size_t)(next * RTILE + lr) * NC + lc);

        // ---- Compute + store 16 rows from xs[cur] ----
        if (active) {
            const float* base = &xs[cur][0][0];
            float4* ob = out4 + (size_t)row0 * Q4 + t;

            if (row0 + RTILE <= nrows) {
                #pragma unroll
                for (int r = 0; r < RTILE; r++) {
                    const int o = r * PAD;
                    float4 v;
                    v.x = base[o + i0] * base[o + i1] * base[o + i2];
                    v.y = base[o + i3] * base[o + i4] * base[o + i5];
                    v.z = base[o + i6] * base[o + i7] * base[o + i8];
                    v.w = base[o + i9] * base[o + ia] * base[o + ib];
                    __stcs(&ob[(size_t)r * Q4], v);
                }
            } else {
                const int rem = nrows - row0;
                for (int r = 0; r < rem; r++) {
                    const int o = r * PAD;
                    float4 v;
                    v.x = base[o + i0] * base[o + i1] * base[o + i2];
                    v.y = base[o + i3] * base[o + i4] * base[o + i5];
                    v.z = base[o + i6] * base[o + i7] * base[o + i8];
                    v.w = base[o + i9] * base[o + ia] * base[o + ib];
                    __stcs(&ob[(size_t)r * Q4], v);
                }
            }
        }

        // ---- Stage prefetched tile into the other buffer ----
        if (do_pre)
            *reinterpret_cast<float4*>(&xs[cur ^ 1][lr][lc]) = pre;

        __syncthreads();   // single barrier: publishes xs[cur^1], retires xs[cur]
    }
}

extern "C" void kernel_launch(void* const* d_in, const int* in_sizes, int n_in,
                              void* d_out, int out_size)
{
    const float* x = (const float*)d_in[0];
    const int nrows = in_sizes[0] / NC;

    const int ntiles = (nrows + RTILE - 1) / RTILE;
    int grid = 148 * 10;                 // 10 blocks/SM (2048-thread cap / 192)
    if (grid > ntiles) grid = ntiles;

    algebraic_expand_kernel<<<grid, BLK>>>(x, (float4*)d_out, nrows);
}